// round 15
// baseline (speedup 1.0000x reference)
#include <cuda_runtime.h>

#define EPSF 1e-6f
#define S 32
#define C 3
#define TILE (S * S)   // 1024
#define PAD 33

// Precomputed Thomas factorizations, 11 time-indices (j=0..5 x-dir, 6..10 y-dir):
//   g_cf2[(j*C+c)*TILE + i*S + r] = (invd, w)
// c_star = -w, so backward sweep is x_i = d_i + w_i * x_{i+1}.
__device__ __align__(128) float2 g_cf2[11 * C * TILE];

// ---------------------------------------------------------------------------
// packed f32x2 + streaming-io helpers (PTX-only)
// ---------------------------------------------------------------------------
__device__ __forceinline__ float2 fma2(float2 a, float2 b, float2 c) {
    unsigned long long au = *reinterpret_cast<unsigned long long*>(&a);
    unsigned long long bu = *reinterpret_cast<unsigned long long*>(&b);
    unsigned long long cu = *reinterpret_cast<unsigned long long*>(&c);
    unsigned long long du;
    asm("fma.rn.f32x2 %0, %1, %2, %3;" : "=l"(du) : "l"(au), "l"(bu), "l"(cu));
    return *reinterpret_cast<float2*>(&du);
}
__device__ __forceinline__ float2 mul2(float2 a, float2 b) {
    unsigned long long au = *reinterpret_cast<unsigned long long*>(&a);
    unsigned long long bu = *reinterpret_cast<unsigned long long*>(&b);
    unsigned long long du;
    asm("mul.rn.f32x2 %0, %1, %2;" : "=l"(du) : "l"(au), "l"(bu));
    return *reinterpret_cast<float2*>(&du);
}

// ---------------------------------------------------------------------------
// Precompute kernel: one thread per (timeIdx, c, row). 11*3*32 = 1056 threads.
// ---------------------------------------------------------------------------
__global__ void precompute_kernel(const float* __restrict__ ab,
                                  const float* __restrict__ bb,
                                  const float* __restrict__ atc,
                                  const float* __restrict__ btc) {
    int tid = blockIdx.x * blockDim.x + threadIdx.x;
    if (tid >= 11 * C * S) return;
    int j   = tid / (C * S);
    int rem = tid % (C * S);
    int c   = rem / S;
    int r   = rem % S;

    float t, fac;
    const float* bp;
    const float* tp;
    int stride;
    if (j < 6) {                       // x-direction, t = j*DT, dt = DT/2
        t   = (float)(j * 0.1);
        fac = 0.05f;
        bp  = ab + (c * S + r) * S;
        tp  = atc + (c * S + r) * S;
        stride = 1;
    } else {                           // y-direction, t = DT/2 + jy*DT, dt = DT
        int jy = j - 6;
        t   = (float)(0.05 + jy * 0.1);
        fac = 0.1f;
        bp  = bb + c * TILE + r;
        tp  = btc + c * TILE + r;
        stride = S;
    }
    float2* out2 = g_cf2 + (j * C + c) * TILE;

    float coef[S];
#pragma unroll
    for (int i = 0; i < S; ++i)
        coef[i] = fmaxf(bp[i * stride] + t * tp[i * stride], EPSF);

    float cs[S];
    cs[0] = (coef[0] + coef[0] + coef[1]) / 3.0f * fac;
#pragma unroll
    for (int i = 1; i < S - 1; ++i)
        cs[i] = (coef[i - 1] + coef[i] + coef[i + 1]) / 3.0f * fac;
    cs[S - 1] = (coef[S - 2] + coef[S - 1] + coef[S - 1]) / 3.0f * fac;

    float wprev = 0.0f;
#pragma unroll
    for (int i = 0; i < S; ++i) {
        float b = 1.0f + 2.0f * cs[i];
        if (i == 0)     b = 1.0f + cs[0];
        if (i == S - 1) b = 1.0f + cs[S - 1];
        float denom = b - cs[i] * wprev + EPSF;
        float invd  = 1.0f / denom;
        float w     = cs[i] * invd;
        out2[i * S + r] = make_float2(invd, w);
        wprev = w;
    }
}

// ---------------------------------------------------------------------------
// Fused-transpose Thomas solve (R13/R14 core, unchanged).
// Canonical slab frame: slab[h*PAD + w] = value at (h, w).
// DIR=0 (X solve): element (h=lane, w=i)  -> slab index lane*PAD + i
// DIR=1 (Y solve): element (h=i, w=lane)  -> slab index i*PAD + lane
// ---------------------------------------------------------------------------
template <int DIR, bool INS, bool OUTS>
__device__ __forceinline__ void solve_t(const float2* __restrict__ cf2, int lane,
                                        float2* __restrict__ v0,
                                        float2* __restrict__ v1,
                                        float*  __restrict__ warr,
                                        float2* __restrict__ sA,
                                        float2* __restrict__ sB) {
#define IDX(i) (DIR == 0 ? (lane * PAD + (i)) : ((i) * PAD + lane))
    float2 cb[2][4];
#pragma unroll
    for (int m = 0; m < 4; ++m)
        cb[0][m] = __ldg(&cf2[m * S + lane]);
    float2 dp0 = make_float2(0.0f, 0.0f);
    float2 dp1 = make_float2(0.0f, 0.0f);
#pragma unroll
    for (int blk = 0; blk < 8; ++blk) {
        if (blk < 7) {
#pragma unroll
            for (int m = 0; m < 4; ++m)
                cb[(blk + 1) & 1][m] = __ldg(&cf2[((blk + 1) * 4 + m) * S + lane]);
        }
#pragma unroll
        for (int m = 0; m < 4; ++m) {
            const int i = blk * 4 + m;
            float2 iw = cb[blk & 1][m];
            warr[i] = iw.y;
            float2 x0 = INS ? sA[IDX(i)] : v0[i];
            float2 x1 = INS ? sB[IDX(i)] : v1[i];
            float2 inv2 = make_float2(iw.x, iw.x);
            float2 w2   = make_float2(iw.y, iw.y);
            float2 t0 = mul2(x0, inv2);
            float2 t1 = mul2(x1, inv2);
            t0 = fma2(w2, dp0, t0);
            t1 = fma2(w2, dp1, t1);
            v0[i] = t0; dp0 = t0;
            v1[i] = t1; dp1 = t1;
        }
    }
    __syncwarp();
    if (OUTS) {
        sA[IDX(31)] = v0[31];
        sB[IDX(31)] = v1[31];
    }
#pragma unroll
    for (int i = S - 2; i >= 0; --i) {
        float2 w2 = make_float2(warr[i], warr[i]);
        float2 r0 = fma2(w2, v0[i + 1], v0[i]);
        float2 r1 = fma2(w2, v1[i + 1], v1[i]);
        v0[i] = r0;
        v1[i] = r1;
        if (OUTS) {
            sA[IDX(i)] = r0;
            sB[IDX(i)] = r1;
        }
    }
    __syncwarp();
#undef IDX
}

// ---------------------------------------------------------------------------
// Main fused ADI kernel: ONE warp per CTA, K=4 tiles as TWO f32x2 pairs.
// PDL: launched with programmatic stream serialization; the table-independent
// io prologue runs concurrently with precompute_kernel, then
// cudaGridDependencySynchronize() gates the first table read.
// ---------------------------------------------------------------------------
__global__ __launch_bounds__(32, 8)
void adi_kernel(const float* __restrict__ uin, float* __restrict__ uout) {
    __shared__ float2 sA[S * PAD];   // pair0 canonical slab
    __shared__ float2 sB[S * PAD];   // pair1 canonical slab

    const int lane   = threadIdx.x;
    const int nquads = gridDim.x / C;                   // 512
    const int cid    = blockIdx.x / nquads;             // c-major grouping
    const int bg     = blockIdx.x % nquads;             // 0..511 batch-quad
    const int base0  = (4 * bg) * C * TILE + cid * TILE;

    float2 v0[S], v1[S];
    float  warr[S];

    // ---- prologue (no table dependence): coalesced LDG -> canonical slabs --
#pragma unroll 8
    for (int i = 0; i < S; ++i) {
        sA[i * PAD + lane] = make_float2(__ldcs(&uin[base0 + 0 * C * TILE + i * S + lane]),
                                         __ldcs(&uin[base0 + 1 * C * TILE + i * S + lane]));
        sB[i * PAD + lane] = make_float2(__ldcs(&uin[base0 + 2 * C * TILE + i * S + lane]),
                                         __ldcs(&uin[base0 + 3 * C * TILE + i * S + lane]));
    }
    __syncwarp();

    // ---- wait for precompute_kernel's tables (PDL dependency) ----
    cudaGridDependencySynchronize();

    const float2* tab = g_cf2 + cid * TILE;   // + j*C*TILE per time index
    const int CT = C * TILE;

    // X0: slab -> slab
    solve_t<0, true, true>(tab + 0 * CT, lane, v0, v1, warr, sA, sB);
    // [Y_it (slab->slab), X_{it+1} (slab->regs), X_{it+1} (regs->slab)] x4
#pragma unroll 1
    for (int it = 0; it < 4; ++it) {
        solve_t<1, true, true >(tab + (6 + it) * CT, lane, v0, v1, warr, sA, sB);
        solve_t<0, true, false>(tab + (it + 1) * CT, lane, v0, v1, warr, sA, sB);
        solve_t<0, false, true>(tab + (it + 1) * CT, lane, v0, v1, warr, sA, sB);
    }
    // Y4: slab -> slab
    solve_t<1, true, true>(tab + 10 * CT, lane, v0, v1, warr, sA, sB);
    // X5: slab -> slab (canonical frame)
    solve_t<0, true, true>(tab + 5 * CT, lane, v0, v1, warr, sA, sB);

    // ---- store: canonical slabs -> coalesced streaming STG ----
#pragma unroll 8
    for (int i = 0; i < S; ++i) {
        float2 a = sA[i * PAD + lane];
        float2 b = sB[i * PAD + lane];
        __stcs(&uout[base0 + 0 * C * TILE + i * S + lane], a.x);
        __stcs(&uout[base0 + 1 * C * TILE + i * S + lane], a.y);
        __stcs(&uout[base0 + 2 * C * TILE + i * S + lane], b.x);
        __stcs(&uout[base0 + 3 * C * TILE + i * S + lane], b.y);
    }
}

// ---------------------------------------------------------------------------
extern "C" void kernel_launch(void* const* d_in, const int* in_sizes, int n_in,
                              void* d_out, int out_size) {
    const float* u   = (const float*)d_in[0];
    const float* ab  = (const float*)d_in[1];
    const float* bb  = (const float*)d_in[2];
    const float* atc = (const float*)d_in[3];
    const float* btc = (const float*)d_in[4];
    float* out = (float*)d_out;

    const int B = in_sizes[0] / (C * TILE);   // 2048

    precompute_kernel<<<(11 * C * S + 127) / 128, 128>>>(ab, bb, atc, btc);

    const int nquads = B / 4;                 // 512

    // PDL launch: adi may start while precompute is still running; the
    // cudaGridDependencySynchronize() inside gates table consumption.
    cudaLaunchConfig_t cfg = {};
    cfg.gridDim  = dim3(nquads * C);          // 1536 one-warp CTAs, c-major
    cfg.blockDim = dim3(32);
    cudaLaunchAttribute attr[1];
    attr[0].id = cudaLaunchAttributeProgrammaticStreamSerialization;
    attr[0].val.programmaticStreamSerializationAllowed = 1;
    cfg.attrs = attr;
    cfg.numAttrs = 1;
    cudaLaunchKernelEx(&cfg, adi_kernel, u, out);
}